// round 11
// baseline (speedup 1.0000x reference)
#include <cuda_runtime.h>
#include <cuda_fp16.h>
#include <cstdint>

// Problem constants (fixed by the benchmark)
#define NN   50000
#define EE   800000
#define DD   128
#define LL   3
#define GG   16
#define OUTD 2

// ---------------- static device scratch (no allocation allowed) ----------------
// Activations live as fp16 hi + e4m3 lo (lo stores (x - fp16(x)) * 2^11).
// g_cnt/g_pool/g_pcnt rely on load-time zero-init for call 1; zero_tail_kernel
// re-zeros them at the end of every call for subsequent replays.
__device__ __half  g_hi[2][2][(size_t)NN * DD];   // [pingpong][type]
__device__ uint8_t g_lo[2][2][(size_t)NN * DD];
__device__ int   g_cnt[2][NN];
__device__ int   g_rowptr[2][NN + 1];
__device__ int   g_cursor[2][NN];
__device__ int   g_csr[2][EE];
__device__ float g_pool[2][GG][DD];
__device__ int   g_pcnt[2][GG];
__device__ __half g_wT_hi[6 * 32768];             // [L*2][128][256] fp16 hi
__device__ __half g_wT_lo[6 * 32768];             // fp16 lo

#define LO_SCALE_F   2048.0f
#define LO_INV_F     4.8828125e-4f               // 2^-11

// ---------------- small helpers ----------------
__device__ __forceinline__ uint32_t smem_u32(const void* p) {
    uint32_t a;
    asm("{ .reg .u64 t; cvta.to.shared.u64 t, %1; cvt.u32.u64 %0, t; }" : "=r"(a) : "l"(p));
    return a;
}
__device__ __forceinline__ void ldsm4(uint32_t* r, uint32_t addr) {
    asm volatile("ldmatrix.sync.aligned.m8n8.x4.shared.b16 {%0,%1,%2,%3}, [%4];"
                 : "=r"(r[0]), "=r"(r[1]), "=r"(r[2]), "=r"(r[3]) : "r"(addr));
}
__device__ __forceinline__ void mma16816(float* c, const uint32_t* a, const uint32_t* b) {
    asm volatile("mma.sync.aligned.m16n8k16.row.col.f32.f16.f16.f32 "
                 "{%0,%1,%2,%3}, {%4,%5,%6,%7}, {%8,%9}, {%0,%1,%2,%3};"
                 : "+f"(c[0]), "+f"(c[1]), "+f"(c[2]), "+f"(c[3])
                 : "r"(a[0]), "r"(a[1]), "r"(a[2]), "r"(a[3]), "r"(b[0]), "r"(b[1]));
}
// pack two floats into e4m3x2: LOW byte = c0, HIGH byte = c1
__device__ __forceinline__ unsigned short enc2(float c0, float c1) {
    unsigned short r;
    asm("cvt.rn.satfinite.e4m3x2.f32 %0, %1, %2;" : "=h"(r) : "f"(c1), "f"(c0));
    return r;
}
// unpack e4m3x2 -> half2 (low byte -> low half)
__device__ __forceinline__ uint32_t dec2(unsigned short w) {
    uint32_t r;
    asm("cvt.rn.f16x2.e4m3x2 %0, %1;" : "=r"(r) : "h"(w));
    return r;
}
// accumulate one gathered edge: 4 cols = uint2 hi (4 halfs) + uint lo (4 fp8)
__device__ __forceinline__ void accE(float4& a, uint2 h, uint32_t l) {
    float2 f0 = __half22float2(*(__half2*)&h.x);
    float2 f1 = __half22float2(*(__half2*)&h.y);
    uint32_t d0 = dec2((unsigned short)(l & 0xffffu));
    uint32_t d1 = dec2((unsigned short)(l >> 16));
    float2 g0 = __half22float2(*(__half2*)&d0);
    float2 g1 = __half22float2(*(__half2*)&d1);
    a.x += fmaf(g0.x, LO_INV_F, f0.x);
    a.y += fmaf(g0.y, LO_INV_F, f0.y);
    a.z += fmaf(g1.x, LO_INV_F, f1.x);
    a.w += fmaf(g1.y, LO_INV_F, f1.y);
}

// ---------------- setup kernel: count + weight prep + input conversion ----------------
#define CNT_BLOCKS  1024
#define WPREP_BLOCKS 64
#define CONV_BLOCKS 128

__global__ void setup_kernel(const int* __restrict__ dst0, const int* __restrict__ dst1,
                             int E,
                             const float* __restrict__ Wl, const float* __restrict__ Wr,
                             const float* __restrict__ x0, const float* __restrict__ x1,
                             int n) {
    if (blockIdx.x < CNT_BLOCKS) {
        int i = blockIdx.x * blockDim.x + threadIdx.x;
        int stride = CNT_BLOCKS * blockDim.x;
        for (; i < 2 * E; i += stride) {
            if (i < E) atomicAdd(&g_cnt[0][dst0[i]], 1);
            else       atomicAdd(&g_cnt[1][dst1[i - E]], 1);
        }
    } else if (blockIdx.x < CNT_BLOCKS + WPREP_BLOCKS) {
        int i = (blockIdx.x - CNT_BLOCKS) * blockDim.x + threadIdx.x;
        int stride = WPREP_BLOCKS * blockDim.x;
        for (int it = i; it < 6 * DD * DD; it += stride) {
            int lt = it >> 14;
            int rem = it & 16383;
            int nrow = rem >> 7;
            int k = rem & 127;
            size_t wb = (size_t)lt * DD * DD;
            size_t ob = (size_t)lt * 32768 + (size_t)nrow * 256;
#pragma unroll
            for (int m = 0; m < 2; m++) {
                const float* W = m ? Wr : Wl;
                float v = W[wb + (size_t)k * DD + nrow];
                __half h = __float2half_rn(v);
                __half l = __float2half_rn(v - __half2float(h));
                g_wT_hi[ob + m * DD + k] = h;
                g_wT_lo[ob + m * DD + k] = l;
            }
        }
    } else {
        // convert fp32 inputs -> hi/lo into ping 0
        int i = (blockIdx.x - CNT_BLOCKS - WPREP_BLOCKS) * blockDim.x + threadIdx.x;
        int stride = CONV_BLOCKS * blockDim.x;
        int pairs = n * DD / 2;
        for (int p = i; p < 2 * pairs; p += stride) {
            int t = (p >= pairs);
            int q = t ? p - pairs : p;
            float2 v = ((const float2*)(t ? x1 : x0))[q];
            __half hx = __float2half_rn(v.x), hy = __float2half_rn(v.y);
            float rx = (v.x - __half2float(hx)) * LO_SCALE_F;
            float ry = (v.y - __half2float(hy)) * LO_SCALE_F;
            *(__half2*)(&g_hi[0][t][(size_t)q * 2]) = __halves2half2(hx, hy);
            *(unsigned short*)(&g_lo[0][t][(size_t)q * 2]) = enc2(rx, ry);
        }
    }
}

// scan + cursor seed
__global__ void scan_both_kernel(int n) {
    __shared__ int part[1024];
    int ty = blockIdx.x;
    const int* cnt = g_cnt[ty];
    int* rowptr = g_rowptr[ty];
    int* cursor = g_cursor[ty];
    int t = threadIdx.x;
    int chunk = (n + 1023) / 1024;
    int beg = t * chunk;
    int end = min(beg + chunk, n);
    int s = 0;
    for (int i = beg; i < end; i++) s += cnt[i];
    part[t] = s;
    __syncthreads();
    for (int off = 1; off < 1024; off <<= 1) {
        int v = (t >= off) ? part[t - off] : 0;
        __syncthreads();
        part[t] += v;
        __syncthreads();
    }
    int run = (t == 0) ? 0 : part[t - 1];
    for (int i = beg; i < end; i++) {
        rowptr[i] = run;
        cursor[i] = run;
        run += cnt[i];
    }
    if (t == 0) rowptr[n] = part[1023];
}

__global__ void fill_both_kernel(const int* __restrict__ e0,
                                 const int* __restrict__ e1, int E) {
    int i = blockIdx.x * blockDim.x + threadIdx.x;
    int stride = gridDim.x * blockDim.x;
    for (; i < 2 * E; i += stride) {
        int t = (i >= E);
        const int* e = t ? e1 : e0;
        int j = t ? i - E : i;
        int d = e[E + j];
        int pos = atomicAdd(&g_cursor[t][d], 1);
        g_csr[t][pos] = e[j];
    }
}

// ---------------- fused layer: gather(mean)->smem + split-fp16 MMA GEMM ----------------
#define AST   40
#define MST   132
#define SMEM_LAYER (128 * MST * 4 + 4 * 128 * AST * 2)   // 108544

__global__ __launch_bounds__(256, 2)
void layer_kernel(const __half* __restrict__ xhi, const uint8_t* __restrict__ xlo,
                  __half* __restrict__ yhi, uint8_t* __restrict__ ylo,
                  const __half* __restrict__ wHi, const __half* __restrict__ wLo,
                  const float* __restrict__ bias,   // [2][128]
                  int n, int tiles_per_type) {
    extern __shared__ __align__(16) char smem[];
    float* meanS = (float*)smem;
    __half* Ah = (__half*)(smem + 128 * MST * 4);
    __half* Al = Ah + 128 * AST;
    __half* Bh = Al + 128 * AST;
    __half* Bl = Bh + 128 * AST;

    int tid = threadIdx.x, wid = tid >> 5, lane = tid & 31;
    int bt = blockIdx.x / tiles_per_type;
    int tile = blockIdx.x - bt * tiles_per_type;
    int row0 = tile * 128;

    const __half* xhi_t = xhi + (size_t)bt * NN * DD;
    const uint8_t* xlo_t = xlo + (size_t)bt * NN * DD;
    __half* yhi_t = yhi + (size_t)bt * NN * DD;
    uint8_t* ylo_t = ylo + (size_t)bt * NN * DD;
    const int* rowptr = g_rowptr[bt];
    const int* csr = g_csr[bt];
    const __half* whi = wHi + (size_t)bt * 32768;
    const __half* wlo = wLo + (size_t)bt * 32768;
    const float* bias_t = bias + bt * DD;

    // ---- phase 1: gather mean (hi fp16 + lo fp8) into smem, fp32 accum ----
    {
        const uint2* xh = (const uint2*)xhi_t;      // 32 uint2 per row
        const uint32_t* xl = (const uint32_t*)xlo_t; // 32 uint per row
#pragma unroll 1
        for (int r = 0; r < 16; r++) {
            int lrow = wid * 16 + r;
            int node = row0 + lrow;
            float4 a0 = make_float4(0.f, 0.f, 0.f, 0.f);
            float4 a1 = a0;
            if (node < n) {
                int b = rowptr[node];
                int e = rowptr[node + 1];
                int j = b;
                if (j + 2 <= e) {
                    int s0 = __ldg(&csr[j]);
                    int s1 = __ldg(&csr[j + 1]);
#pragma unroll 1
                    for (; j + 4 <= e; j += 2) {
                        int p0 = __ldg(&csr[j + 2]);
                        int p1 = __ldg(&csr[j + 3]);
                        uint2 h0 = xh[(size_t)s0 * 32 + lane];
                        uint32_t l0 = xl[(size_t)s0 * 32 + lane];
                        uint2 h1 = xh[(size_t)s1 * 32 + lane];
                        uint32_t l1 = xl[(size_t)s1 * 32 + lane];
                        accE(a0, h0, l0);
                        accE(a1, h1, l1);
                        s0 = p0; s1 = p1;
                    }
                    uint2 h0 = xh[(size_t)s0 * 32 + lane];
                    uint32_t l0 = xl[(size_t)s0 * 32 + lane];
                    uint2 h1 = xh[(size_t)s1 * 32 + lane];
                    uint32_t l1 = xl[(size_t)s1 * 32 + lane];
                    accE(a0, h0, l0);
                    accE(a1, h1, l1);
                    j += 2;
                }
                if (j < e) {
                    int s0 = __ldg(&csr[j]);
                    uint2 h0 = xh[(size_t)s0 * 32 + lane];
                    uint32_t l0 = xl[(size_t)s0 * 32 + lane];
                    accE(a0, h0, l0);
                }
                float ic = 1.0f / (float)max(e - b, 1);
                a0.x = (a0.x + a1.x) * ic;
                a0.y = (a0.y + a1.y) * ic;
                a0.z = (a0.z + a1.z) * ic;
                a0.w = (a0.w + a1.w) * ic;
            }
            *(float4*)(meanS + lrow * MST + lane * 4) = a0;
        }
    }
    __syncthreads();

    // ---- phase 2: GEMM C = [mean|x] @ W' (fp16-split, 3-product) ----
    int wm = wid & 3;
    int wn = wid >> 2;

    float acc[2][8][4];
#pragma unroll
    for (int a = 0; a < 2; a++)
#pragma unroll
        for (int b = 0; b < 8; b++)
#pragma unroll
            for (int c = 0; c < 4; c++) acc[a][b][c] = 0.f;

    uint32_t ahB = smem_u32(Ah), alB = smem_u32(Al);
    uint32_t bhB = smem_u32(Bh), blB = smem_u32(Bl);

    int a_row = wm * 32 + (lane & 7) + ((lane >> 3) & 1) * 8;
    int a_col = (lane >> 4) * 8;
    int b_row = wn * 64 + (lane & 7) + (lane >> 4) * 8;
    int b_col = ((lane >> 3) & 1) * 8;

    int frow = tid >> 1;
    int fcol = (tid & 1) * 16;
    const __half2 S2 = __float2half2_rn(LO_INV_F);

    for (int kb = 0; kb < 8; kb++) {
        // ---- fill A tile ----
        {
            int kc = (kb & 3) * 32;
            __half* ah = Ah + frow * AST + fcol;
            __half* al = Al + frow * AST + fcol;
            if (kb < 4) {
                // mean part: fp32 -> fp16 hi/lo split
#pragma unroll
                for (int i = 0; i < 4; i++) {
                    float4 v = *(const float4*)(meanS + frow * MST + kc + fcol + i * 4);
                    __half hx = __float2half_rn(v.x), hy = __float2half_rn(v.y);
                    __half hz = __float2half_rn(v.z), hw = __float2half_rn(v.w);
                    *(half2*)(ah + i * 4)     = __halves2half2(hx, hy);
                    *(half2*)(ah + i * 4 + 2) = __halves2half2(hz, hw);
                    *(half2*)(al + i * 4)     = __halves2half2(
                        __float2half_rn(v.x - __half2float(hx)),
                        __float2half_rn(v.y - __half2float(hy)));
                    *(half2*)(al + i * 4 + 2) = __halves2half2(
                        __float2half_rn(v.z - __half2float(hz)),
                        __float2half_rn(v.w - __half2float(hw)));
                }
            } else {
                // x part: hi is direct copy, lo is fp8 decode * 2^-11
                int gr = row0 + frow;
                if (gr < n) {
                    const uint4* ph = (const uint4*)(xhi_t + (size_t)gr * DD + kc + fcol);
                    uint4 h0 = ph[0], h1 = ph[1];
                    uint4 lb = *(const uint4*)(xlo_t + (size_t)gr * DD + kc + fcol);
                    *(uint4*)ah = h0;
                    *(uint4*)(ah + 8) = h1;
                    uint32_t u[4] = { lb.x, lb.y, lb.z, lb.w };
                    uint32_t ov[8];
#pragma unroll
                    for (int q = 0; q < 4; q++) {
                        uint32_t dA = dec2((unsigned short)(u[q] & 0xffffu));
                        uint32_t dB = dec2((unsigned short)(u[q] >> 16));
                        __half2 a2 = __hmul2(*(__half2*)&dA, S2);
                        __half2 b2 = __hmul2(*(__half2*)&dB, S2);
                        ov[q * 2]     = *(uint32_t*)&a2;
                        ov[q * 2 + 1] = *(uint32_t*)&b2;
                    }
                    *(uint4*)al = make_uint4(ov[0], ov[1], ov[2], ov[3]);
                    *(uint4*)(al + 8) = make_uint4(ov[4], ov[5], ov[6], ov[7]);
                } else {
                    uint4 z = make_uint4(0, 0, 0, 0);
                    *(uint4*)ah = z; *(uint4*)(ah + 8) = z;
                    *(uint4*)al = z; *(uint4*)(al + 8) = z;
                }
            }
        }
        // ---- fill B tile (pre-split fp16 weights) ----
        {
            int bn = tid >> 1;
            size_t goff = (size_t)bn * 256 + kb * 32 + fcol;
            const int4* gh = (const int4*)(whi + goff);
            const int4* gl = (const int4*)(wlo + goff);
            int4* sh = (int4*)(Bh + bn * AST + fcol);
            int4* sl = (int4*)(Bl + bn * AST + fcol);
            sh[0] = gh[0]; sh[1] = gh[1];
            sl[0] = gl[0]; sl[1] = gl[1];
        }
        __syncthreads();

#pragma unroll
        for (int ks = 0; ks < 2; ks++) {
            int k0 = ks * 16;
            uint32_t ah[2][4], al2[2][4], bf[16];
#pragma unroll
            for (int mt = 0; mt < 2; mt++)
                ldsm4(ah[mt], ahB + ((a_row + mt * 16) * AST + a_col + k0) * 2);
#pragma unroll
            for (int p = 0; p < 4; p++)
                ldsm4(&bf[p * 4], bhB + ((b_row + p * 16) * AST + b_col + k0) * 2);
#pragma unroll
            for (int mt = 0; mt < 2; mt++)
#pragma unroll
                for (int p = 0; p < 4; p++) {
                    mma16816(acc[mt][p * 2 + 0], ah[mt], &bf[p * 4 + 0]);
                    mma16816(acc[mt][p * 2 + 1], ah[mt], &bf[p * 4 + 2]);
                }
#pragma unroll
            for (int mt = 0; mt < 2; mt++)
                ldsm4(al2[mt], alB + ((a_row + mt * 16) * AST + a_col + k0) * 2);
#pragma unroll
            for (int mt = 0; mt < 2; mt++)
#pragma unroll
                for (int p = 0; p < 4; p++) {
                    mma16816(acc[mt][p * 2 + 0], al2[mt], &bf[p * 4 + 0]);
                    mma16816(acc[mt][p * 2 + 1], al2[mt], &bf[p * 4 + 2]);
                }
#pragma unroll
            for (int p = 0; p < 4; p++)
                ldsm4(&bf[p * 4], blB + ((b_row + p * 16) * AST + b_col + k0) * 2);
#pragma unroll
            for (int mt = 0; mt < 2; mt++)
#pragma unroll
                for (int p = 0; p < 4; p++) {
                    mma16816(acc[mt][p * 2 + 0], ah[mt], &bf[p * 4 + 0]);
                    mma16816(acc[mt][p * 2 + 1], ah[mt], &bf[p * 4 + 2]);
                }
        }
        __syncthreads();
    }

    // ---- epilogue: bias + relu -> hi/lo stores ----
#pragma unroll
    for (int mt = 0; mt < 2; mt++) {
#pragma unroll
        for (int rr = 0; rr < 2; rr++) {
            int row = row0 + wm * 32 + mt * 16 + (lane >> 2) + rr * 8;
            if (row >= n) continue;
#pragma unroll
            for (int nt = 0; nt < 8; nt++) {
                int col = wn * 64 + nt * 8 + (lane & 3) * 2;
                float vx = fmaxf(acc[mt][nt][rr * 2 + 0] + __ldg(&bias_t[col + 0]), 0.f);
                float vy = fmaxf(acc[mt][nt][rr * 2 + 1] + __ldg(&bias_t[col + 1]), 0.f);
                __half hx = __float2half_rn(vx), hy = __float2half_rn(vy);
                float rx = (vx - __half2float(hx)) * LO_SCALE_F;
                float ry = (vy - __half2float(hy)) * LO_SCALE_F;
                *(__half2*)(yhi_t + (size_t)row * DD + col) = __halves2half2(hx, hy);
                *(unsigned short*)(ylo_t + (size_t)row * DD + col) = enc2(rx, ry);
            }
        }
    }
}

// ---------------- pooling + head ----------------
#define ROWS_PB 256
__global__ void pool_both_kernel(const __half* __restrict__ xhi,
                                 const uint8_t* __restrict__ xlo,
                                 const int* __restrict__ ba, const int* __restrict__ bb,
                                 int n, int pblocks) {
    int t = (blockIdx.x >= pblocks);
    int blk = t ? blockIdx.x - pblocks : blockIdx.x;
    const __half* xh = xhi + (size_t)t * NN * DD;
    const uint8_t* xl = xlo + (size_t)t * NN * DD;
    const int* batch = t ? bb : ba;
    float* pool = &g_pool[t][0][0];
    int* pcnt = g_pcnt[t];

    int c = threadIdx.x;
    int r0 = blk * ROWS_PB;
    if (r0 >= n) return;
    int r1 = min(r0 + ROWS_PB, n);
    float acc = 0.f;
    int cnt = 0;
    int gcur = batch[r0];
    for (int r = r0; r < r1; r++) {
        int g = batch[r];
        if (g != gcur) {
            atomicAdd(&pool[(size_t)gcur * DD + c], acc);
            if (c == 0) atomicAdd(&pcnt[gcur], cnt);
            acc = 0.f; cnt = 0; gcur = g;
        }
        uint32_t d = dec2((unsigned short)xl[(size_t)r * DD + c]);
        float lo = __half2float(__ushort_as_half((unsigned short)(d & 0xffffu)));
        acc += fmaf(lo, LO_INV_F, __half2float(xh[(size_t)r * DD + c]));
        cnt++;
    }
    atomicAdd(&pool[(size_t)gcur * DD + c], acc);
    if (c == 0) atomicAdd(&pcnt[gcur], cnt);
}

__global__ void final_kernel(const float* __restrict__ linW, const float* __restrict__ linb,
                             float* __restrict__ out) {
    int t32 = threadIdx.x;
    if (t32 >= GG * OUTD) return;
    int g = t32 / OUTD;
    int o = t32 % OUTD;
    float s = linb[o];
    for (int t = 0; t < 2; t++) {
        float ic = 1.0f / fmaxf((float)g_pcnt[t][g], 1.0f);
        const float* p = &g_pool[t][g][0];
        for (int c = 0; c < DD; c++)
            s += p[c] * ic * linW[(t * DD + c) * OUTD + o];
    }
    out[g * OUTD + o] = s;
}

__global__ void zero_tail_kernel() {
    int i = blockIdx.x * blockDim.x + threadIdx.x;
    int stride = gridDim.x * blockDim.x;
    int* cnt = &g_cnt[0][0];
    for (int j = i; j < 2 * NN; j += stride) cnt[j] = 0;
    float* pool = &g_pool[0][0][0];
    for (int j = i; j < 2 * GG * DD; j += stride) pool[j] = 0.f;
    int* pcnt = &g_pcnt[0][0];
    for (int j = i; j < 2 * GG; j += stride) pcnt[j] = 0;
}

// ---------------- launch ----------------
extern "C" void kernel_launch(void* const* d_in, const int* in_sizes, int n_in,
                              void* d_out, int out_size) {
    const float* x_void   = (const float*)d_in[0];
    const float* x_vessel = (const float*)d_in[1];
    const float* Wl   = (const float*)d_in[2];
    const float* bl   = (const float*)d_in[3];
    const float* Wr   = (const float*)d_in[4];
    const float* linW = (const float*)d_in[5];
    const float* linb = (const float*)d_in[6];
    const int* edge_void   = (const int*)d_in[7];
    const int* edge_vessel = (const int*)d_in[8];
    const int* batch_void   = (const int*)d_in[9];
    const int* batch_vessel = (const int*)d_in[10];

    const int n = in_sizes[9];
    const int E = in_sizes[7] / 2;

    __half *hiP, *whiP, *wloP;
    uint8_t* loP;
    cudaGetSymbolAddress((void**)&hiP, g_hi);
    cudaGetSymbolAddress((void**)&loP, g_lo);
    cudaGetSymbolAddress((void**)&whiP, g_wT_hi);
    cudaGetSymbolAddress((void**)&wloP, g_wT_lo);

    cudaFuncSetAttribute(layer_kernel,
                         cudaFuncAttributeMaxDynamicSharedMemorySize, SMEM_LAYER);

    // setup (3 launches)
    setup_kernel<<<CNT_BLOCKS + WPREP_BLOCKS + CONV_BLOCKS, 256>>>(
        edge_void + E, edge_vessel + E, E, Wl, Wr, x_void, x_vessel, n);
    scan_both_kernel<<<2, 1024>>>(n);
    fill_both_kernel<<<1024, 256>>>(edge_void, edge_vessel, E);

    const int tiles = (n + 127) / 128;
    const size_t PP = (size_t)2 * NN * DD;       // pingpong stride

    for (int l = 0; l < LL; l++) {
        int pin = l & 1;                         // 0,1,0
        int pout = 1 - pin;                      // 1,0,1
        layer_kernel<<<2 * tiles, 256, SMEM_LAYER>>>(
            hiP + pin * PP, loP + pin * PP,
            hiP + pout * PP, loP + pout * PP,
            whiP + (size_t)l * 2 * 32768, wloP + (size_t)l * 2 * 32768,
            bl + (size_t)l * 2 * DD, n, tiles);
    }

    // pooling reads ping 1 (output of layer 2)
    int pblocks = (n + ROWS_PB - 1) / ROWS_PB;
    pool_both_kernel<<<2 * pblocks, DD>>>(hiP + PP, loP + PP,
                                          batch_void, batch_vessel, n, pblocks);
    final_kernel<<<1, 32>>>(linW, linb, (float*)d_out);
    zero_tail_kernel<<<64, 256>>>();
}